// round 1
// baseline (speedup 1.0000x reference)
#include <cuda_runtime.h>
#include <math.h>

#define DD 128
#define MAXN 50000
#define MAXE 600000

// ---------------- scratch (no allocations allowed) ----------------
__device__ float g_H0[(size_t)MAXN * DD];
__device__ float g_H1[(size_t)MAXN * DD];
__device__ float g_AGG[(size_t)MAXN * DD];
__device__ int   g_deg[MAXN];
__device__ float g_deginv[MAXN];
__device__ int   g_rowptr[MAXN + 1];
__device__ int   g_cursor[MAXN];
__device__ int   g_col[MAXE];

// ---------------- CSR build ----------------
__global__ void zero_int_kernel(int* __restrict__ p, int n) {
    int i = blockIdx.x * blockDim.x + threadIdx.x;
    if (i < n) p[i] = 0;
}

__global__ void degree_kernel(const int* __restrict__ dst, int* __restrict__ deg, int E) {
    int e = blockIdx.x * blockDim.x + threadIdx.x;
    if (e < E) atomicAdd(&deg[dst[e]], 1);
}

// single-block exclusive scan (N up to 50001 -> 49 chunks of 1024, fast enough)
__global__ void scan_kernel(const int* __restrict__ deg, int* __restrict__ rowptr, int n) {
    __shared__ int s[1024];
    __shared__ int carry;
    int t = threadIdx.x;
    if (t == 0) carry = 0;
    __syncthreads();
    for (int base = 0; base < n; base += 1024) {
        int i = base + t;
        int v = (i < n) ? deg[i] : 0;
        s[t] = v;
        __syncthreads();
        #pragma unroll
        for (int off = 1; off < 1024; off <<= 1) {
            int add = (t >= off) ? s[t - off] : 0;
            __syncthreads();
            s[t] += add;
            __syncthreads();
        }
        if (i < n) rowptr[i] = carry + s[t] - v;
        int total = s[1023];
        __syncthreads();
        if (t == 0) carry += total;
        __syncthreads();
    }
    if (t == 0) rowptr[n] = carry;
}

__global__ void fill_kernel(const int* __restrict__ src, const int* __restrict__ dst,
                            int* __restrict__ cursor, int* __restrict__ col, int E) {
    int e = blockIdx.x * blockDim.x + threadIdx.x;
    if (e < E) {
        int d = dst[e];
        int p = atomicAdd(&cursor[d], 1);
        col[p] = src[e];
    }
}

__global__ void deginv_kernel(const int* __restrict__ deg, float* __restrict__ dinv, int n) {
    int i = blockIdx.x * blockDim.x + threadIdx.x;
    if (i < n) dinv[i] = 1.0f / fmaxf((float)deg[i], 1.0f);
}

// ---------------- mean aggregation: one warp per node ----------------
__global__ void agg_kernel(const float* __restrict__ h, const int* __restrict__ rowptr,
                           const int* __restrict__ colv, const float* __restrict__ dinv,
                           float* __restrict__ out, int n) {
    int warp = (blockIdx.x * blockDim.x + threadIdx.x) >> 5;
    int lane = threadIdx.x & 31;
    if (warp >= n) return;
    int beg = rowptr[warp];
    int end = rowptr[warp + 1];
    float4 acc = make_float4(0.f, 0.f, 0.f, 0.f);
    for (int e = beg; e < end; e++) {
        int s = __ldg(&colv[e]);
        float4 v = *reinterpret_cast<const float4*>(h + (size_t)s * DD + lane * 4);
        acc.x += v.x; acc.y += v.y; acc.z += v.z; acc.w += v.w;
    }
    float di = dinv[warp];
    acc.x *= di; acc.y *= di; acc.z *= di; acc.w *= di;
    *reinterpret_cast<float4*>(out + (size_t)warp * DD + lane * 4) = acc;
}

// ---------------- fused dual GEMM: C = relu(A0@W0 + A1@W1 + bias) ----------------
// M x 128, K = 128 per operand (treated as combined K=256), BM=BN=128, BK=16,
// 256 threads, 8x8 microtile per thread.
__global__ __launch_bounds__(256, 2)
void gemm_fused_kernel(const float* __restrict__ A0, const float* __restrict__ A1,
                       const float* __restrict__ W0, const float* __restrict__ W1,
                       const float* __restrict__ bias, float* __restrict__ C, int M) {
    __shared__ float As[16][128];
    __shared__ float Bs[16][128];

    int tid = threadIdx.x;
    int row0 = blockIdx.x * 128;
    int tm = (tid >> 4) << 3;   // 0..120 step 8
    int tn = (tid & 15) << 3;   // 0..120 step 8

    float acc[8][8];
    #pragma unroll
    for (int i = 0; i < 8; i++)
        #pragma unroll
        for (int j = 0; j < 8; j++) acc[i][j] = 0.f;

    for (int t = 0; t < 16; t++) {
        const float* A = (t < 8) ? A0 : A1;
        const float* W = (t < 8) ? W0 : W1;
        int k0 = (t & 7) * 16;

        // A tile: 128 rows x 16 cols, stored transposed As[k][m]
        #pragma unroll
        for (int i = 0; i < 2; i++) {
            int idx = tid + i * 256;
            int r = idx >> 2;
            int c4 = idx & 3;
            int gr = row0 + r;
            float4 v = make_float4(0.f, 0.f, 0.f, 0.f);
            if (gr < M)
                v = *reinterpret_cast<const float4*>(A + (size_t)gr * 128 + k0 + c4 * 4);
            As[c4 * 4 + 0][r] = v.x;
            As[c4 * 4 + 1][r] = v.y;
            As[c4 * 4 + 2][r] = v.z;
            As[c4 * 4 + 3][r] = v.w;
        }
        // W tile: 16 rows x 128 cols, row-major
        #pragma unroll
        for (int i = 0; i < 2; i++) {
            int idx = tid + i * 256;
            int kr = idx >> 5;
            int c4 = idx & 31;
            *reinterpret_cast<float4*>(&Bs[kr][c4 * 4]) =
                *reinterpret_cast<const float4*>(W + (size_t)(k0 + kr) * 128 + c4 * 4);
        }
        __syncthreads();

        #pragma unroll
        for (int k = 0; k < 16; k++) {
            float ra[8], rb[8];
            *reinterpret_cast<float4*>(ra)     = *reinterpret_cast<float4*>(&As[k][tm]);
            *reinterpret_cast<float4*>(ra + 4) = *reinterpret_cast<float4*>(&As[k][tm + 4]);
            *reinterpret_cast<float4*>(rb)     = *reinterpret_cast<float4*>(&Bs[k][tn]);
            *reinterpret_cast<float4*>(rb + 4) = *reinterpret_cast<float4*>(&Bs[k][tn + 4]);
            #pragma unroll
            for (int i = 0; i < 8; i++)
                #pragma unroll
                for (int j = 0; j < 8; j++)
                    acc[i][j] += ra[i] * rb[j];
        }
        __syncthreads();
    }

    float bv[8];
    *reinterpret_cast<float4*>(bv)     = *reinterpret_cast<const float4*>(bias + tn);
    *reinterpret_cast<float4*>(bv + 4) = *reinterpret_cast<const float4*>(bias + tn + 4);

    #pragma unroll
    for (int i = 0; i < 8; i++) {
        int gr = row0 + tm + i;
        if (gr < M) {
            float o[8];
            #pragma unroll
            for (int j = 0; j < 8; j++) o[j] = fmaxf(acc[i][j] + bv[j], 0.f);
            *reinterpret_cast<float4*>(C + (size_t)gr * 128 + tn)     = *reinterpret_cast<float4*>(o);
            *reinterpret_cast<float4*>(C + (size_t)gr * 128 + tn + 4) = *reinterpret_cast<float4*>(o + 4);
        }
    }
}

// ---------------- final fc: [N,128] @ [128,2] + b ----------------
__global__ void fc_kernel(const float* __restrict__ h, const float* __restrict__ W,
                          const float* __restrict__ b, float* __restrict__ out, int n) {
    int v = blockIdx.x * blockDim.x + threadIdx.x;
    if (v >= n) return;
    float a0 = b[0], a1 = b[1];
    const float* hr = h + (size_t)v * DD;
    #pragma unroll
    for (int k = 0; k < DD; k += 4) {
        float4 x = *reinterpret_cast<const float4*>(hr + k);
        a0 += x.x * W[(k + 0) * 2 + 0]; a1 += x.x * W[(k + 0) * 2 + 1];
        a0 += x.y * W[(k + 1) * 2 + 0]; a1 += x.y * W[(k + 1) * 2 + 1];
        a0 += x.z * W[(k + 2) * 2 + 0]; a1 += x.z * W[(k + 2) * 2 + 1];
        a0 += x.w * W[(k + 3) * 2 + 0]; a1 += x.w * W[(k + 3) * 2 + 1];
    }
    out[v * 2 + 0] = a0;
    out[v * 2 + 1] = a1;
}

// ---------------- driver ----------------
extern "C" void kernel_launch(void* const* d_in, const int* in_sizes, int n_in,
                              void* d_out, int out_size) {
    const float* x   = (const float*)d_in[0];
    const int*   ei  = (const int*)d_in[1];
    const float* Wl  = (const float*)d_in[2];
    const float* Wr  = (const float*)d_in[3];
    const float* bl  = (const float*)d_in[4];
    const float* fcW = (const float*)d_in[5];
    const float* fcb = (const float*)d_in[6];

    int N = in_sizes[0] / DD;
    int E = in_sizes[1] / 2;
    const int* srcv = ei;
    const int* dstv = ei + E;

    float *H0, *H1, *AGG, *DINV;
    int *DEG, *RP, *CUR, *COL;
    cudaGetSymbolAddress((void**)&H0,   g_H0);
    cudaGetSymbolAddress((void**)&H1,   g_H1);
    cudaGetSymbolAddress((void**)&AGG,  g_AGG);
    cudaGetSymbolAddress((void**)&DINV, g_deginv);
    cudaGetSymbolAddress((void**)&DEG,  g_deg);
    cudaGetSymbolAddress((void**)&RP,   g_rowptr);
    cudaGetSymbolAddress((void**)&CUR,  g_cursor);
    cudaGetSymbolAddress((void**)&COL,  g_col);

    // CSR build
    zero_int_kernel<<<(N + 255) / 256, 256>>>(DEG, N);
    degree_kernel<<<(E + 255) / 256, 256>>>(dstv, DEG, E);
    scan_kernel<<<1, 1024>>>(DEG, RP, N);
    cudaMemcpyAsync(CUR, RP, (size_t)N * sizeof(int), cudaMemcpyDeviceToDevice);
    fill_kernel<<<(E + 255) / 256, 256>>>(srcv, dstv, CUR, COL, E);
    deginv_kernel<<<(N + 255) / 256, 256>>>(DEG, DINV, N);

    // layers
    const float* hin = x;
    float* bufs[2] = {H0, H1};
    int agg_blocks = (N * 32 + 255) / 256;
    int gemm_blocks = (N + 127) / 128;
    for (int i = 0; i < 6; i++) {
        agg_kernel<<<agg_blocks, 256>>>(hin, RP, COL, DINV, AGG, N);
        float* hout = bufs[i & 1];
        gemm_fused_kernel<<<gemm_blocks, 256>>>(AGG, hin,
                                                Wl + (size_t)i * DD * DD,
                                                Wr + (size_t)i * DD * DD,
                                                bl + (size_t)i * DD,
                                                hout, N);
        hin = hout;
    }

    fc_kernel<<<(N + 255) / 256, 256>>>(hin, fcW, fcb, (float*)d_out, N);
}

// round 6
// speedup vs baseline: 1.8211x; 1.8211x over previous
#include <cuda_runtime.h>
#include <cuda_bf16.h>
#include <stdint.h>
#include <math.h>

#define DD 128
#define MAXN 50000
#define MAXE 600000
#define NLAYER 6

// ---------------- scratch (no allocations allowed) ----------------
__device__ float g_H0[(size_t)MAXN * DD];
__device__ float g_H1[(size_t)MAXN * DD];
__device__ __nv_bfloat16 g_AHI[(size_t)MAXN * 256];   // [node][0:128)=agg, [128:256)=h
__device__ __nv_bfloat16 g_ALO[(size_t)MAXN * 256];
__device__ __nv_bfloat16 g_WHI[(size_t)NLAYER * 128 * 256];  // [l][n][k] : B[n][k]=W[k][n]
__device__ __nv_bfloat16 g_WLO[(size_t)NLAYER * 128 * 256];
__device__ int   g_deg[MAXN];
__device__ float g_deginv[MAXN];
__device__ int   g_rowptr[MAXN + 1];
__device__ int   g_cursor[MAXN];
__device__ int   g_col[MAXE];

// ---------------- PTX helpers ----------------
__device__ __forceinline__ uint32_t smem_u32(const void* p) {
    uint32_t a;
    asm("{ .reg .u64 t; cvta.to.shared.u64 t, %1; cvt.u32.u64 %0, t; }" : "=r"(a) : "l"(p));
    return a;
}
__device__ __forceinline__ void cp_async16(uint32_t dst, const void* src, int sz) {
    asm volatile("cp.async.cg.shared.global [%0], [%1], 16, %2;\n"
                 :: "r"(dst), "l"(src), "r"(sz) : "memory");
}
__device__ __forceinline__ void mma_bf16(float acc[4], const uint32_t a[4], const uint32_t b[2]) {
    asm volatile(
        "mma.sync.aligned.m16n8k16.row.col.f32.bf16.bf16.f32 "
        "{%0,%1,%2,%3}, {%4,%5,%6,%7}, {%8,%9}, {%0,%1,%2,%3};"
        : "+f"(acc[0]), "+f"(acc[1]), "+f"(acc[2]), "+f"(acc[3])
        : "r"(a[0]), "r"(a[1]), "r"(a[2]), "r"(a[3]), "r"(b[0]), "r"(b[1]));
}

// ---------------- CSR build ----------------
__global__ void zero_int_kernel(int* __restrict__ p, int n) {
    int i = blockIdx.x * blockDim.x + threadIdx.x;
    if (i < n) p[i] = 0;
}
__global__ void degree_kernel(const int* __restrict__ dst, int* __restrict__ deg, int E) {
    int e = blockIdx.x * blockDim.x + threadIdx.x;
    if (e < E) atomicAdd(&deg[dst[e]], 1);
}
__global__ void scan_kernel(const int* __restrict__ deg, int* __restrict__ rowptr, int n) {
    __shared__ int s[1024];
    __shared__ int carry;
    int t = threadIdx.x;
    if (t == 0) carry = 0;
    __syncthreads();
    for (int base = 0; base < n; base += 1024) {
        int i = base + t;
        int v = (i < n) ? deg[i] : 0;
        s[t] = v;
        __syncthreads();
        #pragma unroll
        for (int off = 1; off < 1024; off <<= 1) {
            int add = (t >= off) ? s[t - off] : 0;
            __syncthreads();
            s[t] += add;
            __syncthreads();
        }
        if (i < n) rowptr[i] = carry + s[t] - v;
        int total = s[1023];
        __syncthreads();
        if (t == 0) carry += total;
        __syncthreads();
    }
    if (t == 0) rowptr[n] = carry;
}
__global__ void fill_kernel(const int* __restrict__ src, const int* __restrict__ dst,
                            int* __restrict__ cursor, int* __restrict__ col, int E) {
    int e = blockIdx.x * blockDim.x + threadIdx.x;
    if (e < E) {
        int d = dst[e];
        int p = atomicAdd(&cursor[d], 1);
        col[p] = src[e];
    }
}
__global__ void deginv_kernel(const int* __restrict__ deg, float* __restrict__ dinv, int n) {
    int i = blockIdx.x * blockDim.x + threadIdx.x;
    if (i < n) dinv[i] = 1.0f / fmaxf((float)deg[i], 1.0f);
}

// ---------------- hi/lo split helpers ----------------
__device__ __forceinline__ void split_bf16(float v, __nv_bfloat16& hi, __nv_bfloat16& lo) {
    hi = __float2bfloat16_rn(v);
    lo = __float2bfloat16_rn(v - __bfloat162float(hi));
}

// ---------------- weight prep: B[l][n][k] = W[k][n] split to hi/lo ----------------
__global__ void wprep_kernel(const float* __restrict__ Wl, const float* __restrict__ Wr,
                             __nv_bfloat16* __restrict__ WHI, __nv_bfloat16* __restrict__ WLO) {
    int idx = blockIdx.x * blockDim.x + threadIdx.x;
    if (idx >= NLAYER * 128 * 256) return;
    int k = idx & 255;
    int n = (idx >> 8) & 127;
    int l = idx >> 15;
    float v = (k < 128) ? Wl[(size_t)l * 16384 + k * 128 + n]
                        : Wr[(size_t)l * 16384 + (k - 128) * 128 + n];
    __nv_bfloat16 h, lo;
    split_bf16(v, h, lo);
    WHI[idx] = h;
    WLO[idx] = lo;
}

// ---------------- x -> hi/lo into A cols [128:256) ----------------
__global__ void convx_kernel(const float* __restrict__ x,
                             __nv_bfloat16* __restrict__ AHI, __nv_bfloat16* __restrict__ ALO, int n) {
    int t = blockIdx.x * blockDim.x + threadIdx.x;
    int node = t >> 5, q = t & 31;
    if (node >= n) return;
    float4 v = *reinterpret_cast<const float4*>(x + (size_t)node * 128 + q * 4);
    __nv_bfloat16 h0, h1, h2, h3, l0, l1, l2, l3;
    split_bf16(v.x, h0, l0); split_bf16(v.y, h1, l1);
    split_bf16(v.z, h2, l2); split_bf16(v.w, h3, l3);
    size_t base = (size_t)node * 256 + 128 + q * 4;
    __nv_bfloat162 hp0; hp0.x = h0; hp0.y = h1;
    __nv_bfloat162 hp1; hp1.x = h2; hp1.y = h3;
    __nv_bfloat162 lp0; lp0.x = l0; lp0.y = l1;
    __nv_bfloat162 lp1; lp1.x = l2; lp1.y = l3;
    *reinterpret_cast<__nv_bfloat162*>(AHI + base)     = hp0;
    *reinterpret_cast<__nv_bfloat162*>(AHI + base + 2) = hp1;
    *reinterpret_cast<__nv_bfloat162*>(ALO + base)     = lp0;
    *reinterpret_cast<__nv_bfloat162*>(ALO + base + 2) = lp1;
}

// ---------------- mean aggregation: warp per node -> hi/lo bf16 cols [0:128) ----------------
__global__ void agg_kernel(const float* __restrict__ h, const int* __restrict__ rowptr,
                           const int* __restrict__ colv, const float* __restrict__ dinv,
                           __nv_bfloat16* __restrict__ AHI, __nv_bfloat16* __restrict__ ALO, int n) {
    int warp = (blockIdx.x * blockDim.x + threadIdx.x) >> 5;
    int lane = threadIdx.x & 31;
    if (warp >= n) return;
    int beg = rowptr[warp];
    int end = rowptr[warp + 1];
    float4 acc = make_float4(0.f, 0.f, 0.f, 0.f);
    for (int e = beg; e < end; e++) {
        int s = __ldg(&colv[e]);
        float4 v = *reinterpret_cast<const float4*>(h + (size_t)s * DD + lane * 4);
        acc.x += v.x; acc.y += v.y; acc.z += v.z; acc.w += v.w;
    }
    float di = dinv[warp];
    acc.x *= di; acc.y *= di; acc.z *= di; acc.w *= di;
    __nv_bfloat16 h0, h1, h2, h3, l0, l1, l2, l3;
    split_bf16(acc.x, h0, l0); split_bf16(acc.y, h1, l1);
    split_bf16(acc.z, h2, l2); split_bf16(acc.w, h3, l3);
    size_t base = (size_t)warp * 256 + lane * 4;
    __nv_bfloat162 hp0; hp0.x = h0; hp0.y = h1;
    __nv_bfloat162 hp1; hp1.x = h2; hp1.y = h3;
    __nv_bfloat162 lp0; lp0.x = l0; lp0.y = l1;
    __nv_bfloat162 lp1; lp1.x = l2; lp1.y = l3;
    *reinterpret_cast<__nv_bfloat162*>(AHI + base)     = hp0;
    *reinterpret_cast<__nv_bfloat162*>(AHI + base + 2) = hp1;
    *reinterpret_cast<__nv_bfloat162*>(ALO + base)     = lp0;
    *reinterpret_cast<__nv_bfloat162*>(ALO + base + 2) = lp1;
}

// ---------------- HMMA GEMM: C = relu([agg|h](hi+lo) @ W(hi+lo) + bias) ----------------
// CTA tile 128x128, 8 warps in 2(m) x 4(n) grid, warp tile 64x32.
// K=256 in 8 chunks of 32, cp.async double-buffered.
// SMEM tiles: rows padded to 40 bf16 (80B) -> conflict-free stores and frag loads.
// Split terms per k16: Ah*Bh + Al*Bh + Ah*Bl (fp32 accum).
static constexpr int TILE_B = 128 * 80;      // one matrix tile: 128 rows x 80 bytes
static constexpr int STAGE_B = 4 * TILE_B;   // Ah, Al, Bh, Bl
static constexpr int GEMM_DYN_SMEM = 2 * STAGE_B;  // 81920

__global__ __launch_bounds__(256)
void gemm_mma_kernel(const __nv_bfloat16* __restrict__ AHI,
                     const __nv_bfloat16* __restrict__ ALO,
                     const __nv_bfloat16* __restrict__ BHI,
                     const __nv_bfloat16* __restrict__ BLO,
                     const float* __restrict__ bias,
                     float* __restrict__ Hout,
                     __nv_bfloat16* __restrict__ AHIo,
                     __nv_bfloat16* __restrict__ ALOo,
                     int M) {
    extern __shared__ __align__(16) char sm[];
    __shared__ float s_bias[128];

    const int tid = threadIdx.x;
    const int lane = tid & 31;
    const int wid = tid >> 5;
    const int m0 = (wid >> 2) * 64;   // warp m offset within CTA tile
    const int n0 = (wid & 3) * 32;    // warp n offset
    const int row0 = blockIdx.x * 128;
    const int gid = lane >> 2;        // 0..7
    const int qid = lane & 3;         // 0..3

    if (tid < 128) s_bias[tid] = bias[tid];

    float acc[4][4][4];
    #pragma unroll
    for (int mf = 0; mf < 4; mf++)
        #pragma unroll
        for (int nf = 0; nf < 4; nf++)
            #pragma unroll
            for (int r = 0; r < 4; r++) acc[mf][nf][r] = 0.f;

    auto load_chunk = [&](int c, int s) {
        char* base = sm + s * STAGE_B;
        #pragma unroll
        for (int i = 0; i < 8; i++) {
            int id = tid + i * 256;       // 0..2047
            int tile = id >> 9;           // 0:Ah 1:Al 2:Bh 3:Bl
            int rem = id & 511;
            int r = rem >> 2;             // row 0..127
            int kg = rem & 3;             // 16B group within 32 k-elems
            uint32_t dst = smem_u32(base + tile * TILE_B + r * 80 + kg * 16);
            const __nv_bfloat16* src;
            int sz = 16;
            if (tile == 0)      { src = AHI + (size_t)(row0 + r) * 256 + c * 32 + kg * 8; if (row0 + r >= M) sz = 0; }
            else if (tile == 1) { src = ALO + (size_t)(row0 + r) * 256 + c * 32 + kg * 8; if (row0 + r >= M) sz = 0; }
            else if (tile == 2) { src = BHI + (size_t)r * 256 + c * 32 + kg * 8; }
            else                { src = BLO + (size_t)r * 256 + c * 32 + kg * 8; }
            cp_async16(dst, src, sz);
        }
        asm volatile("cp.async.commit_group;" ::: "memory");
    };

    auto compute = [&](int s) {
        const char* base = sm + s * STAGE_B;
        const char* Ah = base;
        const char* Al = base + TILE_B;
        const char* Bh = base + 2 * TILE_B;
        const char* Bl = base + 3 * TILE_B;
        #pragma unroll
        for (int ks = 0; ks < 2; ks++) {
            const int c0 = ks * 16 + 2 * qid;   // k element index of frag pair
            uint32_t ah[4][4], al[4][4], bh[4][2], blf[4][2];
            #pragma unroll
            for (int mf = 0; mf < 4; mf++) {
                int r = m0 + mf * 16 + gid;
                ah[mf][0] = *(const uint32_t*)(Ah + r * 80 + c0 * 2);
                ah[mf][1] = *(const uint32_t*)(Ah + (r + 8) * 80 + c0 * 2);
                ah[mf][2] = *(const uint32_t*)(Ah + r * 80 + (c0 + 8) * 2);
                ah[mf][3] = *(const uint32_t*)(Ah + (r + 8) * 80 + (c0 + 8) * 2);
                al[mf][0] = *(const uint32_t*)(Al + r * 80 + c0 * 2);
                al[mf][1] = *(const uint32_t*)(Al + (r + 8) * 80 + c0 * 2);
                al[mf][2] = *(const uint32_t*)(Al + r * 80 + (c0 + 8) * 2);
                al[mf][3] = *(const uint32_t*)(Al + (r + 8) * 80 + (c0 + 8) * 2);
            }
            #pragma unroll
            for (int nf = 0; nf < 4; nf++) {
                int rn = n0 + nf * 8 + gid;
                bh[nf][0]  = *(const uint32_t*)(Bh + rn * 80 + c0 * 2);
                bh[nf][1]  = *(const uint32_t*)(Bh + rn * 80 + (c0 + 8) * 2);
                blf[nf][0] = *(const uint32_t*)(Bl + rn * 80 + c0 * 2);
                blf[nf][1] = *(const uint32_t*)(Bl + rn * 80 + (c0 + 8) * 2);
            }
            #pragma unroll
            for (int mf = 0; mf < 4; mf++)
                #pragma unroll
                for (int nf = 0; nf < 4; nf++) {
                    mma_bf16(acc[mf][nf], ah[mf], bh[nf]);
                    mma_bf16(acc[mf][nf], al[mf], bh[nf]);
                    mma_bf16(acc[mf][nf], ah[mf], blf[nf]);
                }
        }
    };

    load_chunk(0, 0);
    #pragma unroll 1
    for (int c = 0; c < 8; c++) {
        if (c + 1 < 8) {
            load_chunk(c + 1, (c + 1) & 1);
            asm volatile("cp.async.wait_group 1;" ::: "memory");
        } else {
            asm volatile("cp.async.wait_group 0;" ::: "memory");
        }
        __syncthreads();
        compute(c & 1);
        __syncthreads();
    }

    // epilogue: bias + relu, write fp32 H and bf16 hi/lo (cols 128..255 of A)
    #pragma unroll
    for (int mf = 0; mf < 4; mf++) {
        int rbase = row0 + m0 + mf * 16 + gid;
        #pragma unroll
        for (int half = 0; half < 2; half++) {
            int row = rbase + half * 8;
            if (row < M) {
                #pragma unroll
                for (int nf = 0; nf < 4; nf++) {
                    int n = n0 + nf * 8 + 2 * qid;
                    float v0 = fmaxf(acc[mf][nf][half * 2 + 0] + s_bias[n], 0.f);
                    float v1 = fmaxf(acc[mf][nf][half * 2 + 1] + s_bias[n + 1], 0.f);
                    *reinterpret_cast<float2*>(Hout + (size_t)row * 128 + n) = make_float2(v0, v1);
                    __nv_bfloat16 h0, h1, l0, l1;
                    split_bf16(v0, h0, l0);
                    split_bf16(v1, h1, l1);
                    __nv_bfloat162 hp; hp.x = h0; hp.y = h1;
                    __nv_bfloat162 lp; lp.x = l0; lp.y = l1;
                    size_t ob = (size_t)row * 256 + 128 + n;
                    *reinterpret_cast<__nv_bfloat162*>(AHIo + ob) = hp;
                    *reinterpret_cast<__nv_bfloat162*>(ALOo + ob) = lp;
                }
            }
        }
    }
}

// ---------------- final fc: [N,128] @ [128,2] + b ----------------
__global__ void fc_kernel(const float* __restrict__ h, const float* __restrict__ W,
                          const float* __restrict__ b, float* __restrict__ out, int n) {
    int v = blockIdx.x * blockDim.x + threadIdx.x;
    if (v >= n) return;
    float a0 = b[0], a1 = b[1];
    const float* hr = h + (size_t)v * DD;
    #pragma unroll
    for (int k = 0; k < DD; k += 4) {
        float4 x = *reinterpret_cast<const float4*>(hr + k);
        a0 += x.x * W[(k + 0) * 2 + 0]; a1 += x.x * W[(k + 0) * 2 + 1];
        a0 += x.y * W[(k + 1) * 2 + 0]; a1 += x.y * W[(k + 1) * 2 + 1];
        a0 += x.z * W[(k + 2) * 2 + 0]; a1 += x.z * W[(k + 2) * 2 + 1];
        a0 += x.w * W[(k + 3) * 2 + 0]; a1 += x.w * W[(k + 3) * 2 + 1];
    }
    out[v * 2 + 0] = a0;
    out[v * 2 + 1] = a1;
}

// ---------------- driver ----------------
extern "C" void kernel_launch(void* const* d_in, const int* in_sizes, int n_in,
                              void* d_out, int out_size) {
    const float* x   = (const float*)d_in[0];
    const int*   ei  = (const int*)d_in[1];
    const float* Wl  = (const float*)d_in[2];
    const float* Wr  = (const float*)d_in[3];
    const float* bl  = (const float*)d_in[4];
    const float* fcW = (const float*)d_in[5];
    const float* fcb = (const float*)d_in[6];

    int N = in_sizes[0] / DD;
    int E = in_sizes[1] / 2;
    const int* srcv = ei;
    const int* dstv = ei + E;

    float *H0, *H1, *DINV;
    __nv_bfloat16 *AHI, *ALO, *WHI, *WLO;
    int *DEG, *RP, *CUR, *COL;
    cudaGetSymbolAddress((void**)&H0,   g_H0);
    cudaGetSymbolAddress((void**)&H1,   g_H1);
    cudaGetSymbolAddress((void**)&AHI,  g_AHI);
    cudaGetSymbolAddress((void**)&ALO,  g_ALO);
    cudaGetSymbolAddress((void**)&WHI,  g_WHI);
    cudaGetSymbolAddress((void**)&WLO,  g_WLO);
    cudaGetSymbolAddress((void**)&DINV, g_deginv);
    cudaGetSymbolAddress((void**)&DEG,  g_deg);
    cudaGetSymbolAddress((void**)&RP,   g_rowptr);
    cudaGetSymbolAddress((void**)&CUR,  g_cursor);
    cudaGetSymbolAddress((void**)&COL,  g_col);

    cudaFuncSetAttribute(gemm_mma_kernel, cudaFuncAttributeMaxDynamicSharedMemorySize,
                         GEMM_DYN_SMEM);

    // CSR build
    zero_int_kernel<<<(N + 255) / 256, 256>>>(DEG, N);
    degree_kernel<<<(E + 255) / 256, 256>>>(dstv, DEG, E);
    scan_kernel<<<1, 1024>>>(DEG, RP, N);
    cudaMemcpyAsync(CUR, RP, (size_t)N * sizeof(int), cudaMemcpyDeviceToDevice);
    fill_kernel<<<(E + 255) / 256, 256>>>(srcv, dstv, CUR, COL, E);
    deginv_kernel<<<(N + 255) / 256, 256>>>(DEG, DINV, N);

    // precision-split prep
    wprep_kernel<<<(NLAYER * 128 * 256 + 255) / 256, 256>>>(Wl, Wr, WHI, WLO);
    convx_kernel<<<(N * 32 + 255) / 256, 256>>>(x, AHI, ALO, N);

    // layers
    const float* hin = x;
    float* bufs[2] = {H0, H1};
    int agg_blocks = (N * 32 + 255) / 256;
    int gemm_blocks = (N + 127) / 128;
    for (int i = 0; i < 6; i++) {
        agg_kernel<<<agg_blocks, 256>>>(hin, RP, COL, DINV, AHI, ALO, N);
        float* hout = bufs[i & 1];
        gemm_mma_kernel<<<gemm_blocks, 256, GEMM_DYN_SMEM>>>(
            AHI, ALO,
            WHI + (size_t)i * 128 * 256,
            WLO + (size_t)i * 128 * 256,
            bl + (size_t)i * DD,
            hout, AHI, ALO, N);
        hin = hout;
    }

    fc_kernel<<<(N + 255) / 256, 256>>>(hin, fcW, fcb, (float*)d_out, N);
}

// round 8
// speedup vs baseline: 2.0642x; 1.1335x over previous
#include <cuda_runtime.h>
#include <cuda_bf16.h>
#include <stdint.h>
#include <math.h>

#define DD 128
#define MAXN 50000
#define MAXE 600000
#define NLAYER 6

// ---------------- scratch (no allocations allowed) ----------------
__device__ float g_H0[(size_t)MAXN * DD];
__device__ float g_H1[(size_t)MAXN * DD];
__device__ __nv_bfloat16 g_AHI[(size_t)MAXN * 256];   // [node][0:128)=agg, [128:256)=h
__device__ __nv_bfloat16 g_ALO[(size_t)MAXN * 256];
__device__ __nv_bfloat16 g_WHI[(size_t)NLAYER * 128 * 256];  // [l][n][k] : B[n][k]=W[k][n]
__device__ __nv_bfloat16 g_WLO[(size_t)NLAYER * 128 * 256];
__device__ int   g_deg[MAXN];
__device__ float g_deginv[MAXN];
__device__ int   g_rowptr[MAXN + 1];
__device__ int   g_cursor[MAXN];
__device__ int   g_col[MAXE];
__device__ int   g_bsum[256];
__device__ int   g_boff[256];

// ---------------- PTX helpers ----------------
__device__ __forceinline__ uint32_t smem_u32(const void* p) {
    uint32_t a;
    asm("{ .reg .u64 t; cvta.to.shared.u64 t, %1; cvt.u32.u64 %0, t; }" : "=r"(a) : "l"(p));
    return a;
}
__device__ __forceinline__ void cp_async16(uint32_t dst, const void* src, int sz) {
    asm volatile("cp.async.cg.shared.global [%0], [%1], 16, %2;\n"
                 :: "r"(dst), "l"(src), "r"(sz) : "memory");
}
__device__ __forceinline__ void mma_bf16(float acc[4], const uint32_t a[4], const uint32_t b[2]) {
    asm volatile(
        "mma.sync.aligned.m16n8k16.row.col.f32.bf16.bf16.f32 "
        "{%0,%1,%2,%3}, {%4,%5,%6,%7}, {%8,%9}, {%0,%1,%2,%3};"
        : "+f"(acc[0]), "+f"(acc[1]), "+f"(acc[2]), "+f"(acc[3])
        : "r"(a[0]), "r"(a[1]), "r"(a[2]), "r"(a[3]), "r"(b[0]), "r"(b[1]));
}

// ---------------- CSR build ----------------
__global__ void zero_int_kernel(int* __restrict__ p, int n) {
    int i = blockIdx.x * blockDim.x + threadIdx.x;
    if (i < n) p[i] = 0;
}
__global__ void degree_kernel(const int* __restrict__ dst, int* __restrict__ deg, int E) {
    int e = blockIdx.x * blockDim.x + threadIdx.x;
    if (e < E) atomicAdd(&deg[dst[e]], 1);
}
// pass 1: per-block exclusive scan (256 entries/block), block total to bsum
__global__ void scan1_kernel(const int* __restrict__ deg, int* __restrict__ rowptr,
                             int* __restrict__ bsum, int n) {
    __shared__ int s[256];
    int t = threadIdx.x;
    int i = blockIdx.x * 256 + t;
    int v = (i < n) ? deg[i] : 0;
    s[t] = v;
    __syncthreads();
    #pragma unroll
    for (int off = 1; off < 256; off <<= 1) {
        int add = (t >= off) ? s[t - off] : 0;
        __syncthreads();
        s[t] += add;
        __syncthreads();
    }
    if (i < n) rowptr[i] = s[t] - v;     // local exclusive
    if (t == 255) bsum[blockIdx.x] = s[255];
}
// pass 2: single-block exclusive scan of block sums
__global__ void scan2_kernel(const int* __restrict__ bsum, int* __restrict__ boff, int nb) {
    __shared__ int s[256];
    int t = threadIdx.x;
    int v = (t < nb) ? bsum[t] : 0;
    s[t] = v;
    __syncthreads();
    #pragma unroll
    for (int off = 1; off < 256; off <<= 1) {
        int add = (t >= off) ? s[t - off] : 0;
        __syncthreads();
        s[t] += add;
        __syncthreads();
    }
    if (t < nb) boff[t] = s[t] - v;
}
// pass 3: add offsets; also write cursor, deginv, rowptr[n]
__global__ void scan3_kernel(int* __restrict__ rowptr, int* __restrict__ cursor,
                             const int* __restrict__ boff, const int* __restrict__ deg,
                             float* __restrict__ dinv, int n, int E) {
    int i = blockIdx.x * blockDim.x + threadIdx.x;
    if (i < n) {
        int r = rowptr[i] + boff[i >> 8];
        rowptr[i] = r;
        cursor[i] = r;
        dinv[i] = 1.0f / fmaxf((float)deg[i], 1.0f);
    }
    if (i == 0) rowptr[n] = E;
}
__global__ void fill_kernel(const int* __restrict__ src, const int* __restrict__ dst,
                            int* __restrict__ cursor, int* __restrict__ col, int E) {
    int e = blockIdx.x * blockDim.x + threadIdx.x;
    if (e < E) {
        int d = dst[e];
        int p = atomicAdd(&cursor[d], 1);
        col[p] = src[e];
    }
}

// ---------------- hi/lo split helpers ----------------
__device__ __forceinline__ void split_bf16(float v, __nv_bfloat16& hi, __nv_bfloat16& lo) {
    hi = __float2bfloat16_rn(v);
    lo = __float2bfloat16_rn(v - __bfloat162float(hi));
}

// ---------------- weight prep: B[l][n][k] = W[k][n] split to hi/lo ----------------
__global__ void wprep_kernel(const float* __restrict__ Wl, const float* __restrict__ Wr,
                             __nv_bfloat16* __restrict__ WHI, __nv_bfloat16* __restrict__ WLO) {
    int idx = blockIdx.x * blockDim.x + threadIdx.x;
    if (idx >= NLAYER * 128 * 256) return;
    int k = idx & 255;
    int n = (idx >> 8) & 127;
    int l = idx >> 15;
    float v = (k < 128) ? Wl[(size_t)l * 16384 + k * 128 + n]
                        : Wr[(size_t)l * 16384 + (k - 128) * 128 + n];
    __nv_bfloat16 h, lo;
    split_bf16(v, h, lo);
    WHI[idx] = h;
    WLO[idx] = lo;
}

// ---------------- x -> hi/lo into A cols [128:256) ----------------
__global__ void convx_kernel(const float* __restrict__ x,
                             __nv_bfloat16* __restrict__ AHI, __nv_bfloat16* __restrict__ ALO, int n) {
    int t = blockIdx.x * blockDim.x + threadIdx.x;
    int node = t >> 5, q = t & 31;
    if (node >= n) return;
    float4 v = *reinterpret_cast<const float4*>(x + (size_t)node * 128 + q * 4);
    __nv_bfloat16 h0, h1, h2, h3, l0, l1, l2, l3;
    split_bf16(v.x, h0, l0); split_bf16(v.y, h1, l1);
    split_bf16(v.z, h2, l2); split_bf16(v.w, h3, l3);
    size_t base = (size_t)node * 256 + 128 + q * 4;
    __nv_bfloat162 hp0; hp0.x = h0; hp0.y = h1;
    __nv_bfloat162 hp1; hp1.x = h2; hp1.y = h3;
    __nv_bfloat162 lp0; lp0.x = l0; lp0.y = l1;
    __nv_bfloat162 lp1; lp1.x = l2; lp1.y = l3;
    *reinterpret_cast<__nv_bfloat162*>(AHI + base)     = hp0;
    *reinterpret_cast<__nv_bfloat162*>(AHI + base + 2) = hp1;
    *reinterpret_cast<__nv_bfloat162*>(ALO + base)     = lp0;
    *reinterpret_cast<__nv_bfloat162*>(ALO + base + 2) = lp1;
}

// ---------------- mean aggregation: warp per node, 4-edge unroll ----------------
__global__ void agg_kernel(const float* __restrict__ h, const int* __restrict__ rowptr,
                           const int* __restrict__ colv, const float* __restrict__ dinv,
                           __nv_bfloat16* __restrict__ AHI, __nv_bfloat16* __restrict__ ALO, int n) {
    int warp = (blockIdx.x * blockDim.x + threadIdx.x) >> 5;
    int lane = threadIdx.x & 31;
    if (warp >= n) return;
    int beg = rowptr[warp];
    int end = rowptr[warp + 1];
    float4 acc = make_float4(0.f, 0.f, 0.f, 0.f);
    int e = beg;
    for (; e + 4 <= end; e += 4) {
        int s0 = __ldg(&colv[e + 0]);
        int s1 = __ldg(&colv[e + 1]);
        int s2 = __ldg(&colv[e + 2]);
        int s3 = __ldg(&colv[e + 3]);
        float4 v0 = __ldg(reinterpret_cast<const float4*>(h + (size_t)s0 * DD + lane * 4));
        float4 v1 = __ldg(reinterpret_cast<const float4*>(h + (size_t)s1 * DD + lane * 4));
        float4 v2 = __ldg(reinterpret_cast<const float4*>(h + (size_t)s2 * DD + lane * 4));
        float4 v3 = __ldg(reinterpret_cast<const float4*>(h + (size_t)s3 * DD + lane * 4));
        acc.x += (v0.x + v1.x) + (v2.x + v3.x);
        acc.y += (v0.y + v1.y) + (v2.y + v3.y);
        acc.z += (v0.z + v1.z) + (v2.z + v3.z);
        acc.w += (v0.w + v1.w) + (v2.w + v3.w);
    }
    for (; e < end; e++) {
        int s = __ldg(&colv[e]);
        float4 v = __ldg(reinterpret_cast<const float4*>(h + (size_t)s * DD + lane * 4));
        acc.x += v.x; acc.y += v.y; acc.z += v.z; acc.w += v.w;
    }
    float di = dinv[warp];
    acc.x *= di; acc.y *= di; acc.z *= di; acc.w *= di;
    __nv_bfloat16 h0, h1, h2, h3, l0, l1, l2, l3;
    split_bf16(acc.x, h0, l0); split_bf16(acc.y, h1, l1);
    split_bf16(acc.z, h2, l2); split_bf16(acc.w, h3, l3);
    size_t base = (size_t)warp * 256 + lane * 4;
    __nv_bfloat162 hp0; hp0.x = h0; hp0.y = h1;
    __nv_bfloat162 hp1; hp1.x = h2; hp1.y = h3;
    __nv_bfloat162 lp0; lp0.x = l0; lp0.y = l1;
    __nv_bfloat162 lp1; lp1.x = l2; lp1.y = l3;
    *reinterpret_cast<__nv_bfloat162*>(AHI + base)     = hp0;
    *reinterpret_cast<__nv_bfloat162*>(AHI + base + 2) = hp1;
    *reinterpret_cast<__nv_bfloat162*>(ALO + base)     = lp0;
    *reinterpret_cast<__nv_bfloat162*>(ALO + base + 2) = lp1;
}

// ---------------- HMMA GEMM: C = relu([agg|h](hi+lo) @ W(hi+lo) + bias) ----------------
// CTA tile 128x128, 8 warps in 2(m) x 4(n) grid, warp tile 64x32.
// K=256 in 8 chunks of 32, cp.async double-buffered.
// SMEM tiles: rows padded to 40 bf16 (80B) -> conflict-free stores and frag loads.
// Split terms per k16: Ah*Bh + Al*Bh + Ah*Bl (fp32 accum).
static constexpr int TILE_B = 128 * 80;      // one matrix tile: 128 rows x 80 bytes
static constexpr int STAGE_B = 4 * TILE_B;   // Ah, Al, Bh, Bl
static constexpr int GEMM_DYN_SMEM = 2 * STAGE_B;  // 81920

__global__ __launch_bounds__(256)
void gemm_mma_kernel(const __nv_bfloat16* __restrict__ AHI,
                     const __nv_bfloat16* __restrict__ ALO,
                     const __nv_bfloat16* __restrict__ BHI,
                     const __nv_bfloat16* __restrict__ BLO,
                     const float* __restrict__ bias,
                     float* __restrict__ Hout,
                     __nv_bfloat16* __restrict__ AHIo,
                     __nv_bfloat16* __restrict__ ALOo,
                     int M) {
    extern __shared__ __align__(16) char sm[];
    __shared__ float s_bias[128];

    const int tid = threadIdx.x;
    const int lane = tid & 31;
    const int wid = tid >> 5;
    const int m0 = (wid >> 2) * 64;   // warp m offset within CTA tile
    const int n0 = (wid & 3) * 32;    // warp n offset
    const int row0 = blockIdx.x * 128;
    const int gid = lane >> 2;        // 0..7
    const int qid = lane & 3;         // 0..3

    if (tid < 128) s_bias[tid] = bias[tid];

    float acc[4][4][4];
    #pragma unroll
    for (int mf = 0; mf < 4; mf++)
        #pragma unroll
        for (int nf = 0; nf < 4; nf++)
            #pragma unroll
            for (int r = 0; r < 4; r++) acc[mf][nf][r] = 0.f;

    auto load_chunk = [&](int c, int s) {
        char* base = sm + s * STAGE_B;
        #pragma unroll
        for (int i = 0; i < 8; i++) {
            int id = tid + i * 256;       // 0..2047
            int tile = id >> 9;           // 0:Ah 1:Al 2:Bh 3:Bl
            int rem = id & 511;
            int r = rem >> 2;             // row 0..127
            int kg = rem & 3;             // 16B group within 32 k-elems
            uint32_t dst = smem_u32(base + tile * TILE_B + r * 80 + kg * 16);
            const __nv_bfloat16* src;
            int sz = 16;
            if (tile == 0)      { src = AHI + (size_t)(row0 + r) * 256 + c * 32 + kg * 8; if (row0 + r >= M) sz = 0; }
            else if (tile == 1) { src = ALO + (size_t)(row0 + r) * 256 + c * 32 + kg * 8; if (row0 + r >= M) sz = 0; }
            else if (tile == 2) { src = BHI + (size_t)r * 256 + c * 32 + kg * 8; }
            else                { src = BLO + (size_t)r * 256 + c * 32 + kg * 8; }
            cp_async16(dst, src, sz);
        }
        asm volatile("cp.async.commit_group;" ::: "memory");
    };

    auto compute = [&](int s) {
        const char* base = sm + s * STAGE_B;
        const char* Ah = base;
        const char* Al = base + TILE_B;
        const char* Bh = base + 2 * TILE_B;
        const char* Bl = base + 3 * TILE_B;
        #pragma unroll
        for (int ks = 0; ks < 2; ks++) {
            const int c0 = ks * 16 + 2 * qid;   // k element index of frag pair
            uint32_t ah[4][4], al[4][4], bh[4][2], blf[4][2];
            #pragma unroll
            for (int mf = 0; mf < 4; mf++) {
                int r = m0 + mf * 16 + gid;
                ah[mf][0] = *(const uint32_t*)(Ah + r * 80 + c0 * 2);
                ah[mf][1] = *(const uint32_t*)(Ah + (r + 8) * 80 + c0 * 2);
                ah[mf][2] = *(const uint32_t*)(Ah + r * 80 + (c0 + 8) * 2);
                ah[mf][3] = *(const uint32_t*)(Ah + (r + 8) * 80 + (c0 + 8) * 2);
                al[mf][0] = *(const uint32_t*)(Al + r * 80 + c0 * 2);
                al[mf][1] = *(const uint32_t*)(Al + (r + 8) * 80 + c0 * 2);
                al[mf][2] = *(const uint32_t*)(Al + r * 80 + (c0 + 8) * 2);
                al[mf][3] = *(const uint32_t*)(Al + (r + 8) * 80 + (c0 + 8) * 2);
            }
            #pragma unroll
            for (int nf = 0; nf < 4; nf++) {
                int rn = n0 + nf * 8 + gid;
                bh[nf][0]  = *(const uint32_t*)(Bh + rn * 80 + c0 * 2);
                bh[nf][1]  = *(const uint32_t*)(Bh + rn * 80 + (c0 + 8) * 2);
                blf[nf][0] = *(const uint32_t*)(Bl + rn * 80 + c0 * 2);
                blf[nf][1] = *(const uint32_t*)(Bl + rn * 80 + (c0 + 8) * 2);
            }
            #pragma unroll
            for (int mf = 0; mf < 4; mf++)
                #pragma unroll
                for (int nf = 0; nf < 4; nf++) {
                    mma_bf16(acc[mf][nf], ah[mf], bh[nf]);
                    mma_bf16(acc[mf][nf], al[mf], bh[nf]);
                    mma_bf16(acc[mf][nf], ah[mf], blf[nf]);
                }
        }
    };

    load_chunk(0, 0);
    #pragma unroll 1
    for (int c = 0; c < 8; c++) {
        if (c + 1 < 8) {
            load_chunk(c + 1, (c + 1) & 1);
            asm volatile("cp.async.wait_group 1;" ::: "memory");
        } else {
            asm volatile("cp.async.wait_group 0;" ::: "memory");
        }
        __syncthreads();
        compute(c & 1);
        __syncthreads();
    }

    // epilogue: bias + relu, write fp32 H and bf16 hi/lo (cols 128..255 of A)
    #pragma unroll
    for (int mf = 0; mf < 4; mf++) {
        int rbase = row0 + m0 + mf * 16 + gid;
        #pragma unroll
        for (int half = 0; half < 2; half++) {
            int row = rbase + half * 8;
            if (row < M) {
                #pragma unroll
                for (int nf = 0; nf < 4; nf++) {
                    int n = n0 + nf * 8 + 2 * qid;
                    float v0 = fmaxf(acc[mf][nf][half * 2 + 0] + s_bias[n], 0.f);
                    float v1 = fmaxf(acc[mf][nf][half * 2 + 1] + s_bias[n + 1], 0.f);
                    *reinterpret_cast<float2*>(Hout + (size_t)row * 128 + n) = make_float2(v0, v1);
                    __nv_bfloat16 h0, h1, l0, l1;
                    split_bf16(v0, h0, l0);
                    split_bf16(v1, h1, l1);
                    __nv_bfloat162 hp; hp.x = h0; hp.y = h1;
                    __nv_bfloat162 lp; lp.x = l0; lp.y = l1;
                    size_t ob = (size_t)row * 256 + 128 + n;
                    *reinterpret_cast<__nv_bfloat162*>(AHIo + ob) = hp;
                    *reinterpret_cast<__nv_bfloat162*>(ALOo + ob) = lp;
                }
            }
        }
    }
}

// ---------------- final fc: [N,128] @ [128,2] + b ----------------
__global__ void fc_kernel(const float* __restrict__ h, const float* __restrict__ W,
                          const float* __restrict__ b, float* __restrict__ out, int n) {
    int v = blockIdx.x * blockDim.x + threadIdx.x;
    if (v >= n) return;
    float a0 = b[0], a1 = b[1];
    const float* hr = h + (size_t)v * DD;
    #pragma unroll
    for (int k = 0; k < DD; k += 4) {
        float4 x = *reinterpret_cast<const float4*>(hr + k);
        a0 += x.x * W[(k + 0) * 2 + 0]; a1 += x.x * W[(k + 0) * 2 + 1];
        a0 += x.y * W[(k + 1) * 2 + 0]; a1 += x.y * W[(k + 1) * 2 + 1];
        a0 += x.z * W[(k + 2) * 2 + 0]; a1 += x.z * W[(k + 2) * 2 + 1];
        a0 += x.w * W[(k + 3) * 2 + 0]; a1 += x.w * W[(k + 3) * 2 + 1];
    }
    out[v * 2 + 0] = a0;
    out[v * 2 + 1] = a1;
}

// ---------------- driver ----------------
extern "C" void kernel_launch(void* const* d_in, const int* in_sizes, int n_in,
                              void* d_out, int out_size) {
    const float* x   = (const float*)d_in[0];
    const int*   ei  = (const int*)d_in[1];
    const float* Wl  = (const float*)d_in[2];
    const float* Wr  = (const float*)d_in[3];
    const float* bl  = (const float*)d_in[4];
    const float* fcW = (const float*)d_in[5];
    const float* fcb = (const float*)d_in[6];

    int N = in_sizes[0] / DD;
    int E = in_sizes[1] / 2;
    const int* srcv = ei;
    const int* dstv = ei + E;

    float *H0, *H1, *DINV;
    __nv_bfloat16 *AHI, *ALO, *WHI, *WLO;
    int *DEG, *RP, *CUR, *COL, *BSUM, *BOFF;
    cudaGetSymbolAddress((void**)&H0,   g_H0);
    cudaGetSymbolAddress((void**)&H1,   g_H1);
    cudaGetSymbolAddress((void**)&AHI,  g_AHI);
    cudaGetSymbolAddress((void**)&ALO,  g_ALO);
    cudaGetSymbolAddress((void**)&WHI,  g_WHI);
    cudaGetSymbolAddress((void**)&WLO,  g_WLO);
    cudaGetSymbolAddress((void**)&DINV, g_deginv);
    cudaGetSymbolAddress((void**)&DEG,  g_deg);
    cudaGetSymbolAddress((void**)&RP,   g_rowptr);
    cudaGetSymbolAddress((void**)&CUR,  g_cursor);
    cudaGetSymbolAddress((void**)&COL,  g_col);
    cudaGetSymbolAddress((void**)&BSUM, g_bsum);
    cudaGetSymbolAddress((void**)&BOFF, g_boff);

    cudaFuncSetAttribute(gemm_mma_kernel, cudaFuncAttributeMaxDynamicSharedMemorySize,
                         GEMM_DYN_SMEM);

    int nb = (N + 255) / 256;

    // CSR build
    zero_int_kernel<<<nb, 256>>>(DEG, N);
    degree_kernel<<<(E + 255) / 256, 256>>>(dstv, DEG, E);
    scan1_kernel<<<nb, 256>>>(DEG, RP, BSUM, N);
    scan2_kernel<<<1, 256>>>(BSUM, BOFF, nb);
    scan3_kernel<<<nb, 256>>>(RP, CUR, BOFF, DEG, DINV, N, E);
    fill_kernel<<<(E + 255) / 256, 256>>>(srcv, dstv, CUR, COL, E);

    // precision-split prep
    wprep_kernel<<<(NLAYER * 128 * 256 + 255) / 256, 256>>>(Wl, Wr, WHI, WLO);
    convx_kernel<<<(N * 32 + 255) / 256, 256>>>(x, AHI, ALO, N);

    // layers
    const float* hin = x;
    float* bufs[2] = {H0, H1};
    int agg_blocks = (N * 32 + 255) / 256;
    int gemm_blocks = (N + 127) / 128;
    for (int i = 0; i < 6; i++) {
        agg_kernel<<<agg_blocks, 256>>>(hin, RP, COL, DINV, AHI, ALO, N);
        float* hout = bufs[i & 1];
        gemm_mma_kernel<<<gemm_blocks, 256, GEMM_DYN_SMEM>>>(
            AHI, ALO,
            WHI + (size_t)i * 128 * 256,
            WLO + (size_t)i * 128 * 256,
            bl + (size_t)i * DD,
            hout, AHI, ALO, N);
        hin = hout;
    }

    fc_kernel<<<(N + 255) / 256, 256>>>(hin, fcW, fcb, (float*)d_out, N);
}